// round 3
// baseline (speedup 1.0000x reference)
#include <cuda_runtime.h>
#include <math.h>

#define BB 32
#define TT 512
#define HH 1024
#define LL 256
#define VV 13

// ---- scratch (static device globals: no allocation allowed) ----
__device__ float g_h0[BB * HH];                 // 128 KB
__device__ float g_c[BB * HH];                  // 128 KB
__device__ float g_hs[(size_t)BB * TT * HH];    // 64 MB, layout [b][t][h]
__device__ float g_part[512];                   // per-CTA loss partials (16 CTAs per b)

// ------------------------------------------------------------------
// zero c state
// ------------------------------------------------------------------
__global__ void k_zero() {
    int i = blockIdx.x * blockDim.x + threadIdx.x;
    if (i < BB * HH) g_c[i] = 0.f;
}

// ------------------------------------------------------------------
// h0 = relu(latent @ Wz^T + bz)
// ------------------------------------------------------------------
__global__ void k_h0(const float* __restrict__ latent,
                     const float* __restrict__ Wz,
                     const float* __restrict__ bz) {
    __shared__ float lat[LL];
    int b = blockIdx.x;
    for (int k = threadIdx.x; k < LL; k += blockDim.x) lat[k] = latent[b * LL + k];
    __syncthreads();
    for (int j = threadIdx.x; j < HH; j += blockDim.x) {
        const float4* w = (const float4*)(Wz + (size_t)j * LL);
        float s = bz[j];
#pragma unroll 8
        for (int k4 = 0; k4 < LL / 4; ++k4) {
            float4 wv = w[k4];
            s += wv.x * lat[k4 * 4 + 0] + wv.y * lat[k4 * 4 + 1]
               + wv.z * lat[k4 * 4 + 2] + wv.w * lat[k4 * 4 + 3];
        }
        g_h0[b * HH + j] = fmaxf(s, 0.f);
    }
}

// ------------------------------------------------------------------
// One LSTM timestep. 128 CTAs x 128 threads.
// CTA m owns units [m*8, m*8+8): 32 gate rows (4 gates per unit),
// so gate GEMM + pointwise are CTA-local (no inter-CTA dependency).
// ------------------------------------------------------------------
#define KC 64
#define AP 68   // As row pitch (floats): 68*4B = 17*16B, float4-aligned
#define BP 34   // Bs row pitch (k-major), even for float2 reads

__global__ __launch_bounds__(128) void k_step(
    int t,
    const float* __restrict__ W_hh,   // [4H, H]
    const float* __restrict__ W_ih,   // [4H, V]
    const float* __restrict__ b_ih,
    const float* __restrict__ b_hh,
    const int*   __restrict__ labels) // [B, T]
{
    __shared__ float As[32 * AP];     // W_hh tile: rows (g*8+ul) x KC
    __shared__ float Bs[KC * BP];     // h_prev tile transposed: [k][b]

    const int tid = threadIdx.x;
    const int tx = tid & 15;          // batch pair 0..15
    const int ty = tid >> 4;          // local unit 0..7
    const int u0 = blockIdx.x * 8;

    float acc[4][2] = {};

    for (int kc = 0; kc < HH; kc += KC) {
        // stage A: 32 rows x 64 = 512 float4, 4 per thread
#pragma unroll
        for (int q = 0; q < 4; ++q) {
            int i = tid + q * 128;
            int row = i >> 4;                  // 0..31
            int kq = (i & 15) << 2;            // 0..60
            int g = row >> 3, ul = row & 7;
            float4 v = *(const float4*)(W_hh + (size_t)(g * HH + u0 + ul) * HH + kc + kq);
            *(float4*)(As + row * AP + kq) = v;
        }
        // stage B (transposed): 32 b x 64 k = 2048 floats, 16 per thread
#pragma unroll
        for (int q = 0; q < 16; ++q) {
            int i = q * 128 + tid;
            int k = i & (KC - 1);
            int b = i >> 6;
            float v;
            if (t == 0) v = g_h0[b * HH + kc + k];
            else        v = g_hs[((size_t)b * TT + (t - 1)) * HH + kc + k];
            Bs[k * BP + b] = v;
        }
        __syncthreads();

#pragma unroll 8
        for (int k = 0; k < KC; ++k) {
            float2 bb = *(const float2*)(Bs + k * BP + (tx << 1));
            float a0 = As[(0 * 8 + ty) * AP + k];
            float a1 = As[(1 * 8 + ty) * AP + k];
            float a2 = As[(2 * 8 + ty) * AP + k];
            float a3 = As[(3 * 8 + ty) * AP + k];
            acc[0][0] += a0 * bb.x; acc[0][1] += a0 * bb.y;
            acc[1][0] += a1 * bb.x; acc[1][1] += a1 * bb.y;
            acc[2][0] += a2 * bb.x; acc[2][1] += a2 * bb.y;
            acc[3][0] += a3 * bb.x; acc[3][1] += a3 * bb.y;
        }
        __syncthreads();
    }

    // pointwise LSTM cell update (torch gate order: i, f, g, o)
    const int unit = u0 + ty;
#pragma unroll
    for (int n = 0; n < 2; ++n) {
        const int b = (tx << 1) + n;
        float gate[4];
        int lbl = (t > 0) ? labels[b * TT + t - 1] : 0;
#pragma unroll
        for (int g = 0; g < 4; ++g) {
            int row = g * HH + unit;
            float x = acc[g][n] + b_ih[row] + b_hh[row];
            if (t > 0) x += W_ih[row * VV + lbl];   // one-hot input = column gather
            gate[g] = x;
        }
        float ig = 1.f / (1.f + expf(-gate[0]));
        float fg = 1.f / (1.f + expf(-gate[1]));
        float gg = tanhf(gate[2]);
        float og = 1.f / (1.f + expf(-gate[3]));
        size_t cidx = (size_t)b * HH + unit;
        float c = fg * g_c[cidx] + ig * gg;
        g_c[cidx] = c;
        g_hs[((size_t)b * TT + t) * HH + unit] = og * tanhf(c);
    }
}

// ------------------------------------------------------------------
// Output head, fused: a = relu([h,lat] @ Wnl^T + bnl) ;
// logits = a @ Wout^T + bout ; nll at label ; masked sum.
// One CTA = 32 consecutive (b,t) rows (same b). 512 CTAs x 128 threads.
// ------------------------------------------------------------------
#define OKC 32
#define FP 33   // Fs pitch
#define WT 68   // Wst pitch: 68*4B = 17*16B, float4-aligned
#define ASP 66  // aS pitch
#define WOP 66  // Wos pitch

__global__ __launch_bounds__(128) void k_out(
    const float* __restrict__ latent,
    const int*   __restrict__ labels,
    const int*   __restrict__ lengths,
    const float* __restrict__ Wnl,   // [H, H+L]
    const float* __restrict__ bnl,   // [H]
    const float* __restrict__ Wout,  // [V, H]
    const float* __restrict__ bout)  // [V]
{
    __shared__ float Fs[32 * FP];        // feature tile [row][k]
    __shared__ float Wst[OKC * WT];      // Wnl tile transposed [k][jl]
    __shared__ float aS[32 * ASP];       // relu activations [row][jl]
    __shared__ float Wos[VV * WOP];      // Wout chunk [v][jl]
    __shared__ float Ls[32 * 16];        // logits accumulators
    __shared__ float lat_s[LL];
    __shared__ float red[4];

    const int tid = threadIdx.x;
    const int r0 = blockIdx.x * 32;      // global row = b*T + t
    const int b = r0 / TT;
    const int txj = tid & 15;            // j group (4 each)
    const int tyr = tid >> 4;            // row group (4 each)

    for (int idx = tid; idx < 32 * 16; idx += 128) Ls[idx] = 0.f;
    for (int k = tid; k < LL; k += 128) lat_s[k] = latent[b * LL + k];

    for (int jc = 0; jc < HH; jc += 64) {
        float acc[4][4] = {};
        for (int kc = 0; kc < HH + LL; kc += OKC) {
            __syncthreads();
            // stage features: 32 rows x 32 k
#pragma unroll
            for (int q = 0; q < 8; ++q) {
                int i = q * 128 + tid;
                int k = i & 31;
                int row = i >> 5;
                int kk = kc + k;
                float v = (kk < HH) ? g_hs[(size_t)(r0 + row) * HH + kk]
                                    : lat_s[kk - HH];
                Fs[row * FP + k] = v;
            }
            // stage Wnl transposed: 64 j x 32 k
#pragma unroll
            for (int q = 0; q < 4; ++q) {
                int i = q * 128 + tid;           // 0..511 float4
                int jl = i >> 3;                 // 0..63
                int kq = (i & 7) << 2;           // 0..28
                float4 v = *(const float4*)(Wnl + (size_t)(jc + jl) * (HH + LL) + kc + kq);
                Wst[(kq + 0) * WT + jl] = v.x;
                Wst[(kq + 1) * WT + jl] = v.y;
                Wst[(kq + 2) * WT + jl] = v.z;
                Wst[(kq + 3) * WT + jl] = v.w;
            }
            __syncthreads();
#pragma unroll 4
            for (int k = 0; k < OKC; ++k) {
                float4 wv = *(const float4*)(Wst + k * WT + (txj << 2));
                float f0 = Fs[(tyr * 4 + 0) * FP + k];
                float f1 = Fs[(tyr * 4 + 1) * FP + k];
                float f2 = Fs[(tyr * 4 + 2) * FP + k];
                float f3 = Fs[(tyr * 4 + 3) * FP + k];
                acc[0][0] += f0 * wv.x; acc[0][1] += f0 * wv.y; acc[0][2] += f0 * wv.z; acc[0][3] += f0 * wv.w;
                acc[1][0] += f1 * wv.x; acc[1][1] += f1 * wv.y; acc[1][2] += f1 * wv.z; acc[1][3] += f1 * wv.w;
                acc[2][0] += f2 * wv.x; acc[2][1] += f2 * wv.y; acc[2][2] += f2 * wv.z; acc[2][3] += f2 * wv.w;
                acc[3][0] += f3 * wv.x; acc[3][1] += f3 * wv.y; acc[3][2] += f3 * wv.z; acc[3][3] += f3 * wv.w;
            }
        }
        __syncthreads();
        // relu + bias -> aS ; stage Wout chunk
#pragma unroll
        for (int ri = 0; ri < 4; ++ri)
#pragma unroll
            for (int ji = 0; ji < 4; ++ji) {
                int j = (txj << 2) + ji;
                aS[(tyr * 4 + ri) * ASP + j] = fmaxf(acc[ri][ji] + bnl[jc + j], 0.f);
            }
        for (int idx = tid; idx < VV * 64; idx += 128) {
            int v = idx >> 6, jl = idx & 63;
            Wos[v * WOP + jl] = Wout[(size_t)v * HH + jc + jl];
        }
        __syncthreads();
        // logits accumulation (tiny GEMM to V=13)
        for (int idx = tid; idx < 32 * VV; idx += 128) {
            int row = idx / VV, v = idx - row * VV;
            float s = 0.f;
#pragma unroll 8
            for (int jl = 0; jl < 64; ++jl)
                s += aS[row * ASP + jl] * Wos[v * WOP + jl];
            Ls[row * 16 + v] += s;
        }
        __syncthreads();
    }

    // log-softmax + masked NLL, reduce to one partial per CTA (deterministic)
    float val = 0.f;
    if (tid < 32) {
        int row = tid;
        int t = (r0 + row) % TT;
        float m = -1e30f;
#pragma unroll
        for (int v = 0; v < VV; ++v) m = fmaxf(m, Ls[row * 16 + v] + bout[v]);
        float s = 0.f;
#pragma unroll
        for (int v = 0; v < VV; ++v) s += expf(Ls[row * 16 + v] + bout[v] - m);
        float lse = m + logf(s);
        int lbl = labels[b * TT + t];
        float nll = lse - (Ls[row * 16 + lbl] + bout[lbl]);
        if (t < lengths[b]) val = nll;
#pragma unroll
        for (int o = 16; o > 0; o >>= 1) val += __shfl_down_sync(0xffffffffu, val, o);
        if (row == 0) g_part[blockIdx.x] = val;
    }
}

// ------------------------------------------------------------------
// finalize: out[1+b] = sum of 16 partials ; out[0] = total
// ------------------------------------------------------------------
__global__ void k_final(float* __restrict__ out, int out_size) {
    int b = threadIdx.x;   // 0..31
    float s = 0.f;
#pragma unroll
    for (int i = 0; i < 16; ++i) s += g_part[b * 16 + i];
    if (1 + b < out_size) out[1 + b] = s;
    float tot = s;
#pragma unroll
    for (int o = 16; o > 0; o >>= 1) tot += __shfl_down_sync(0xffffffffu, tot, o);
    if (b == 0) out[0] = tot;
}

// ------------------------------------------------------------------
extern "C" void kernel_launch(void* const* d_in, const int* in_sizes, int n_in,
                              void* d_out, int out_size) {
    // metadata order = setup_inputs dict order
    // 0: seq_input (unused — one-hot reconstructed from labels)
    const float* latent  = (const float*)d_in[1];
    const int*   labels  = (const int*)d_in[2];
    const int*   lengths = (const int*)d_in[3];
    const float* W_ih    = (const float*)d_in[4];
    const float* W_hh    = (const float*)d_in[5];
    const float* b_ih    = (const float*)d_in[6];
    const float* b_hh    = (const float*)d_in[7];
    const float* Wz      = (const float*)d_in[8];
    const float* bz      = (const float*)d_in[9];
    const float* Wnl     = (const float*)d_in[10];
    const float* bnl     = (const float*)d_in[11];
    const float* Wout    = (const float*)d_in[12];
    const float* bout    = (const float*)d_in[13];
    float* out = (float*)d_out;

    k_zero<<<(BB * HH + 255) / 256, 256>>>();
    k_h0<<<BB, 256>>>(latent, Wz, bz);
    for (int t = 0; t < TT; ++t)
        k_step<<<128, 128>>>(t, W_hh, W_ih, b_ih, b_hh, labels);
    k_out<<<(BB * TT) / 32, 128>>>(latent, labels, lengths, Wnl, bnl, Wout, bout);
    k_final<<<1, 32>>>(out, out_size);
}

// round 4
// speedup vs baseline: 1.7730x; 1.7730x over previous
#include <cuda_runtime.h>
#include <math.h>

#define BB 32
#define TT 512
#define HH 1024
#define LL 256
#define VV 13

// ---- scratch (static device globals: no allocation allowed) ----
__device__ float g_h0[BB * HH];                 // 128 KB
__device__ float g_hs[(size_t)BB * TT * HH];    // 64 MB, layout [b][t][h]
__device__ float g_part[512];                   // per-CTA loss partials
__device__ unsigned g_bar;                      // software grid barrier counter

typedef unsigned long long ull;
union F4U { float4 f; ull u[2]; };

__device__ __forceinline__ void ffma2(ull& d, ull a, ull b) {
    asm("fma.rn.f32x2 %0, %1, %2, %0;" : "+l"(d) : "l"(a), "l"(b));
}
__device__ __forceinline__ float pair_sum(ull v) {
    float x, y;
    asm("mov.b64 {%0, %1}, %2;" : "=f"(x), "=f"(y) : "l"(v));
    return x + y;
}
__device__ __forceinline__ unsigned ld_acq(const unsigned* p) {
    unsigned v;
    asm volatile("ld.acquire.gpu.global.u32 %0, [%1];" : "=r"(v) : "l"(p) : "memory");
    return v;
}
__device__ __forceinline__ void red_rel(unsigned* p, unsigned v) {
    asm volatile("red.release.gpu.global.add.u32 [%0], %1;" :: "l"(p), "r"(v) : "memory");
}

// SMEM layout for k_lstm (dynamic)
#define SM_A     0          // W_hh slice: 512 kp * 256B = 131072
#define SM_B     131072     // 8 warps * 2 * 16kp * 256B = 65536 (reused for partials)
#define SM_BIAS  196608     // 32 floats
#define SM_TOTAL 196736

__global__ void k_zero() {
    if (threadIdx.x == 0 && blockIdx.x == 0) g_bar = 0u;
}

// ------------------------------------------------------------------
// h0 = relu(latent @ Wz^T + bz)
// ------------------------------------------------------------------
__global__ void k_h0(const float* __restrict__ latent,
                     const float* __restrict__ Wz,
                     const float* __restrict__ bz) {
    __shared__ float lat[LL];
    int b = blockIdx.x;
    for (int k = threadIdx.x; k < LL; k += blockDim.x) lat[k] = latent[b * LL + k];
    __syncthreads();
    for (int j = threadIdx.x; j < HH; j += blockDim.x) {
        const float4* w = (const float4*)(Wz + (size_t)j * LL);
        float s = bz[j];
#pragma unroll 8
        for (int k4 = 0; k4 < LL / 4; ++k4) {
            float4 wv = w[k4];
            s += wv.x * lat[k4 * 4 + 0] + wv.y * lat[k4 * 4 + 1]
               + wv.z * lat[k4 * 4 + 2] + wv.w * lat[k4 * 4 + 3];
        }
        g_h0[b * HH + j] = fmaxf(s, 0.f);
    }
}

// ------------------------------------------------------------------
// Persistent LSTM recurrence. 128 CTAs (1/SM), 256 threads (8 warps).
// CTA m owns units [8m, 8m+8) = 32 gate rows; its W_hh slice lives in
// SMEM as k-pair float2, layout As[kp 0..511][unit 0..7][gate 0..3].
// Split-K over warps (warp w: k in [128w,128w+128)); lane (lb,lr) tile =
// 4 gates of unit lr x 8 batches (b = 8*lb..8*lb+7). fma.rn.f32x2 inner.
// Grid barrier between steps on g_bar (release/acquire).
// ------------------------------------------------------------------
__global__ void __launch_bounds__(256, 1) k_lstm(
    const float* __restrict__ W_hh,   // [4H, H]
    const float* __restrict__ W_ih,   // [4H, V]
    const float* __restrict__ b_ih,
    const float* __restrict__ b_hh,
    const int*   __restrict__ labels) // [B, T]
{
    extern __shared__ char sm[];
    float* cbias = (float*)(sm + SM_BIAS);

    const int tid  = threadIdx.x;
    const int w    = tid >> 5;
    const int lane = tid & 31;
    const int lr   = lane & 7;    // unit within CTA
    const int lb   = lane >> 3;   // batch group (8 each)
    const int u0   = blockIdx.x * 8;

    // ---- one-time: W_hh slice -> SMEM as k-pairs; combined biases ----
    for (int i = tid; i < 32 * 512; i += 256) {
        int kp = i & 511, row = i >> 9;       // row = u*4+g
        int u = row >> 2, g = row & 3;
        ((float2*)sm)[kp * 32 + u * 4 + g] =
            *(const float2*)(W_hh + (size_t)(g * HH + u0 + u) * HH + 2 * kp);
    }
    if (tid < 32) {
        int u = tid >> 2, g = tid & 3;
        cbias[tid] = b_ih[g * HH + u0 + u] + b_hh[g * HH + u0 + u];
    }

    const int pu = tid & 7;       // pointwise: unit
    const int pb = tid >> 3;      // pointwise: batch 0..31
    float c_loc = 0.f;
    char* buf0 = sm + SM_B + w * 8192;
    __syncthreads();

    for (int t = 0; t < TT; ++t) {
        if (t > 0) {
            if (tid == 0) {
                unsigned tgt = 128u * (unsigned)t;
                while (ld_acq(&g_bar) < tgt) {}
            }
            __syncthreads();
        }

        // staging source: lane loads batch = lane, k-slice of its warp
        const float* src = (t == 0) ? (g_h0 + lane * HH)
                                    : (g_hs + ((size_t)lane * TT + (t - 1)) * HH);
        const float4* s4 = (const float4*)(src + w * 128);

        float4 v[8];
#pragma unroll
        for (int j = 0; j < 8; ++j) v[j] = s4[j];   // prefetch sub-chunk 0

        ull acc[4][8];
#pragma unroll
        for (int g = 0; g < 4; ++g)
#pragma unroll
            for (int c = 0; c < 8; ++c) acc[g][c] = 0ull;

#pragma unroll
        for (int sc = 0; sc < 4; ++sc) {
            char* buf = buf0 + (sc & 1) * 4096;
            // store prefetched 32 k (16 kp) transposed: B[kp][b]
#pragma unroll
            for (int j = 0; j < 8; ++j) {
                *(float2*)(buf + (2 * j) * 256 + lane * 8)     = make_float2(v[j].x, v[j].y);
                *(float2*)(buf + (2 * j + 1) * 256 + lane * 8) = make_float2(v[j].z, v[j].w);
            }
            __syncwarp();
            if (sc < 3) {
#pragma unroll
                for (int j = 0; j < 8; ++j) v[j] = s4[(sc + 1) * 8 + j];
            }
            const char* Ab = sm + (size_t)(w * 64 + sc * 16) * 256;
#pragma unroll
            for (int kp = 0; kp < 16; ++kp) {
                F4U qa0, qa1;
                qa0.f = *(const float4*)(Ab + kp * 256 + lr * 32);
                qa1.f = *(const float4*)(Ab + kp * 256 + lr * 32 + 16);
                const char* bp = buf + kp * 256 + lb * 64;
                F4U q0, q1, q2, q3;
                q0.f = *(const float4*)(bp);
                q1.f = *(const float4*)(bp + 16);
                q2.f = *(const float4*)(bp + 32);
                q3.f = *(const float4*)(bp + 48);
                ull a0 = qa0.u[0], a1 = qa0.u[1], a2 = qa1.u[0], a3 = qa1.u[1];
                ull b0 = q0.u[0], b1 = q0.u[1], b2 = q1.u[0], b3 = q1.u[1];
                ull b4 = q2.u[0], b5 = q2.u[1], b6 = q3.u[0], b7 = q3.u[1];
                ffma2(acc[0][0], a0, b0); ffma2(acc[0][1], a0, b1);
                ffma2(acc[0][2], a0, b2); ffma2(acc[0][3], a0, b3);
                ffma2(acc[0][4], a0, b4); ffma2(acc[0][5], a0, b5);
                ffma2(acc[0][6], a0, b6); ffma2(acc[0][7], a0, b7);
                ffma2(acc[1][0], a1, b0); ffma2(acc[1][1], a1, b1);
                ffma2(acc[1][2], a1, b2); ffma2(acc[1][3], a1, b3);
                ffma2(acc[1][4], a1, b4); ffma2(acc[1][5], a1, b5);
                ffma2(acc[1][6], a1, b6); ffma2(acc[1][7], a1, b7);
                ffma2(acc[2][0], a2, b0); ffma2(acc[2][1], a2, b1);
                ffma2(acc[2][2], a2, b2); ffma2(acc[2][3], a2, b3);
                ffma2(acc[2][4], a2, b4); ffma2(acc[2][5], a2, b5);
                ffma2(acc[2][6], a2, b6); ffma2(acc[2][7], a2, b7);
                ffma2(acc[3][0], a3, b0); ffma2(acc[3][1], a3, b1);
                ffma2(acc[3][2], a3, b2); ffma2(acc[3][3], a3, b3);
                ffma2(acc[3][4], a3, b4); ffma2(acc[3][5], a3, b5);
                ffma2(acc[3][6], a3, b6); ffma2(acc[3][7], a3, b7);
            }
            __syncwarp();
        }

        // ---- split-K reduction: partials into B region (after all reads) ----
        __syncthreads();
        float* P = (float*)(sm + SM_B);   // [w][b][u] x float4 gates
#pragma unroll
        for (int c = 0; c < 8; ++c) {
            int b = lb * 8 + c;
            float4 g4 = make_float4(pair_sum(acc[0][c]), pair_sum(acc[1][c]),
                                    pair_sum(acc[2][c]), pair_sum(acc[3][c]));
            *(float4*)(P + ((w * 32 + b) * 8 + lr) * 4) = g4;
        }
        __syncthreads();

        // ---- reduce over 8 warps + pointwise cell (i,f,g,o order) ----
        float4 s = make_float4(0.f, 0.f, 0.f, 0.f);
#pragma unroll
        for (int ww = 0; ww < 8; ++ww) {
            float4 pv = *(const float4*)(P + ((ww * 32 + pb) * 8 + pu) * 4);
            s.x += pv.x; s.y += pv.y; s.z += pv.z; s.w += pv.w;
        }
        float gi = s.x + cbias[pu * 4 + 0];
        float gf = s.y + cbias[pu * 4 + 1];
        float gg = s.z + cbias[pu * 4 + 2];
        float go = s.w + cbias[pu * 4 + 3];
        if (t > 0) {   // one-hot input = column gather of W_ih
            int lbl = labels[pb * TT + t - 1];
            int ub  = u0 + pu;
            gi += W_ih[(size_t)(0 * HH + ub) * VV + lbl];
            gf += W_ih[(size_t)(1 * HH + ub) * VV + lbl];
            gg += W_ih[(size_t)(2 * HH + ub) * VV + lbl];
            go += W_ih[(size_t)(3 * HH + ub) * VV + lbl];
        }
        float is = 1.f / (1.f + expf(-gi));
        float fs = 1.f / (1.f + expf(-gf));
        float gt = tanhf(gg);
        float os = 1.f / (1.f + expf(-go));
        c_loc = fs * c_loc + is * gt;
        g_hs[((size_t)pb * TT + t) * HH + u0 + pu] = os * tanhf(c_loc);

        __syncthreads();   // h writes + P reads done before release / reuse
        if (tid == 0) red_rel(&g_bar, 1u);
    }
}

// ------------------------------------------------------------------
// Output head (unchanged, known-good): fused GEMM->relu->GEMM->
// log-softmax->masked NLL. One CTA = 32 consecutive (b,t) rows.
// ------------------------------------------------------------------
#define OKC 32
#define FP 33
#define WT 68
#define ASP 66
#define WOP 66

__global__ void __launch_bounds__(128) k_out(
    const float* __restrict__ latent,
    const int*   __restrict__ labels,
    const int*   __restrict__ lengths,
    const float* __restrict__ Wnl,   // [H, H+L]
    const float* __restrict__ bnl,
    const float* __restrict__ Wout,  // [V, H]
    const float* __restrict__ bout)
{
    __shared__ float Fs[32 * FP];
    __shared__ float Wst[OKC * WT];
    __shared__ float aS[32 * ASP];
    __shared__ float Wos[VV * WOP];
    __shared__ float Ls[32 * 16];
    __shared__ float lat_s[LL];

    const int tid = threadIdx.x;
    const int r0 = blockIdx.x * 32;
    const int b = r0 / TT;
    const int txj = tid & 15;
    const int tyr = tid >> 4;

    for (int idx = tid; idx < 32 * 16; idx += 128) Ls[idx] = 0.f;
    for (int k = tid; k < LL; k += 128) lat_s[k] = latent[b * LL + k];

    for (int jc = 0; jc < HH; jc += 64) {
        float acc[4][4] = {};
        for (int kc = 0; kc < HH + LL; kc += OKC) {
            __syncthreads();
#pragma unroll
            for (int q = 0; q < 8; ++q) {
                int i = q * 128 + tid;
                int k = i & 31;
                int row = i >> 5;
                int kk = kc + k;
                float v = (kk < HH) ? g_hs[(size_t)(r0 + row) * HH + kk]
                                    : lat_s[kk - HH];
                Fs[row * FP + k] = v;
            }
#pragma unroll
            for (int q = 0; q < 4; ++q) {
                int i = q * 128 + tid;
                int jl = i >> 3;
                int kq = (i & 7) << 2;
                float4 v = *(const float4*)(Wnl + (size_t)(jc + jl) * (HH + LL) + kc + kq);
                Wst[(kq + 0) * WT + jl] = v.x;
                Wst[(kq + 1) * WT + jl] = v.y;
                Wst[(kq + 2) * WT + jl] = v.z;
                Wst[(kq + 3) * WT + jl] = v.w;
            }
            __syncthreads();
#pragma unroll 4
            for (int k = 0; k < OKC; ++k) {
                float4 wv = *(const float4*)(Wst + k * WT + (txj << 2));
                float f0 = Fs[(tyr * 4 + 0) * FP + k];
                float f1 = Fs[(tyr * 4 + 1) * FP + k];
                float f2 = Fs[(tyr * 4 + 2) * FP + k];
                float f3 = Fs[(tyr * 4 + 3) * FP + k];
                acc[0][0] += f0 * wv.x; acc[0][1] += f0 * wv.y; acc[0][2] += f0 * wv.z; acc[0][3] += f0 * wv.w;
                acc[1][0] += f1 * wv.x; acc[1][1] += f1 * wv.y; acc[1][2] += f1 * wv.z; acc[1][3] += f1 * wv.w;
                acc[2][0] += f2 * wv.x; acc[2][1] += f2 * wv.y; acc[2][2] += f2 * wv.z; acc[2][3] += f2 * wv.w;
                acc[3][0] += f3 * wv.x; acc[3][1] += f3 * wv.y; acc[3][2] += f3 * wv.z; acc[3][3] += f3 * wv.w;
            }
        }
        __syncthreads();
#pragma unroll
        for (int ri = 0; ri < 4; ++ri)
#pragma unroll
            for (int ji = 0; ji < 4; ++ji) {
                int j = (txj << 2) + ji;
                aS[(tyr * 4 + ri) * ASP + j] = fmaxf(acc[ri][ji] + bnl[jc + j], 0.f);
            }
        for (int idx = tid; idx < VV * 64; idx += 128) {
            int v = idx >> 6, jl = idx & 63;
            Wos[v * WOP + jl] = Wout[(size_t)v * HH + jc + jl];
        }
        __syncthreads();
        for (int idx = tid; idx < 32 * VV; idx += 128) {
            int row = idx / VV, v = idx - row * VV;
            float s = 0.f;
#pragma unroll 8
            for (int jl = 0; jl < 64; ++jl)
                s += aS[row * ASP + jl] * Wos[v * WOP + jl];
            Ls[row * 16 + v] += s;
        }
        __syncthreads();
    }

    float val = 0.f;
    if (tid < 32) {
        int row = tid;
        int t = (r0 + row) % TT;
        float m = -1e30f;
#pragma unroll
        for (int v = 0; v < VV; ++v) m = fmaxf(m, Ls[row * 16 + v] + bout[v]);
        float s = 0.f;
#pragma unroll
        for (int v = 0; v < VV; ++v) s += expf(Ls[row * 16 + v] + bout[v] - m);
        float lse = m + logf(s);
        int lbl = labels[b * TT + t];
        float nll = lse - (Ls[row * 16 + lbl] + bout[lbl]);
        if (t < lengths[b]) val = nll;
#pragma unroll
        for (int o = 16; o > 0; o >>= 1) val += __shfl_down_sync(0xffffffffu, val, o);
        if (row == 0) g_part[blockIdx.x] = val;
    }
}

// ------------------------------------------------------------------
__global__ void k_final(float* __restrict__ out, int out_size) {
    int b = threadIdx.x;   // 0..31
    float s = 0.f;
#pragma unroll
    for (int i = 0; i < 16; ++i) s += g_part[b * 16 + i];
    if (1 + b < out_size) out[1 + b] = s;
    float tot = s;
#pragma unroll
    for (int o = 16; o > 0; o >>= 1) tot += __shfl_down_sync(0xffffffffu, tot, o);
    if (b == 0) out[0] = tot;
}

// ------------------------------------------------------------------
extern "C" void kernel_launch(void* const* d_in, const int* in_sizes, int n_in,
                              void* d_out, int out_size) {
    const float* latent  = (const float*)d_in[1];
    const int*   labels  = (const int*)d_in[2];
    const int*   lengths = (const int*)d_in[3];
    const float* W_ih    = (const float*)d_in[4];
    const float* W_hh    = (const float*)d_in[5];
    const float* b_ih    = (const float*)d_in[6];
    const float* b_hh    = (const float*)d_in[7];
    const float* Wz      = (const float*)d_in[8];
    const float* bz      = (const float*)d_in[9];
    const float* Wnl     = (const float*)d_in[10];
    const float* bnl     = (const float*)d_in[11];
    const float* Wout    = (const float*)d_in[12];
    const float* bout    = (const float*)d_in[13];
    float* out = (float*)d_out;

    cudaFuncSetAttribute(k_lstm, cudaFuncAttributeMaxDynamicSharedMemorySize, SM_TOTAL);

    k_zero<<<1, 32>>>();
    k_h0<<<BB, 256>>>(latent, Wz, bz);
    k_lstm<<<128, 256, SM_TOTAL>>>(W_hh, W_ih, b_ih, b_hh, labels);
    k_out<<<(BB * TT) / 32, 128>>>(latent, labels, lengths, Wnl, bnl, Wout, bout);
    k_final<<<1, 32>>>(out, out_size);
}

// round 5
// speedup vs baseline: 2.0812x; 1.1738x over previous
#include <cuda_runtime.h>
#include <math.h>

#define BB 32
#define TT 512
#define HH 1024
#define LL 256
#define VV 13

// ---- scratch (static device globals: no allocation allowed) ----
__device__ float g_h0[BB * HH];                 // 128 KB
__device__ float g_hs[(size_t)BB * TT * HH];    // 64 MB, layout [b][t][h]
__device__ float g_part[512];                   // per-CTA loss partials
__device__ unsigned g_bar;                      // software grid barrier counter

typedef unsigned long long ull;
union F4U { float4 f; ull u[2]; };

__device__ __forceinline__ void ffma2(ull& d, ull a, ull b) {
    asm("fma.rn.f32x2 %0, %1, %2, %0;" : "+l"(d) : "l"(a), "l"(b));
}
__device__ __forceinline__ float pair_sum(ull v) {
    float x, y;
    asm("mov.b64 {%0, %1}, %2;" : "=f"(x), "=f"(y) : "l"(v));
    return x + y;
}
__device__ __forceinline__ unsigned ld_acq(const unsigned* p) {
    unsigned v;
    asm volatile("ld.acquire.gpu.global.u32 %0, [%1];" : "=r"(v) : "l"(p) : "memory");
    return v;
}
__device__ __forceinline__ void red_rel(unsigned* p, unsigned v) {
    asm volatile("red.release.gpu.global.add.u32 [%0], %1;" :: "l"(p), "r"(v) : "memory");
}

// SMEM layout for k_lstm (dynamic)
// A: W_hh slice, 512 kp * 32 rows * 8B = 131072
// B: 16 warps * 2 buffers * (8 kp * 272B) = 69632  (reused for split-K partials: 65536)
// bias: 32 floats
#define SM_A     0
#define SM_B     131072
#define SM_BUF1  2176          // 8 kp * 272
#define SM_BUFW  (2 * SM_BUF1) // 4352 per warp
#define SM_BIAS  (SM_B + 16 * SM_BUFW)   // 200704
#define SM_TOTAL (SM_BIAS + 128)         // 200832

__global__ void k_zero() {
    if (threadIdx.x == 0 && blockIdx.x == 0) g_bar = 0u;
}

// ------------------------------------------------------------------
// h0 = relu(latent @ Wz^T + bz)
// ------------------------------------------------------------------
__global__ void k_h0(const float* __restrict__ latent,
                     const float* __restrict__ Wz,
                     const float* __restrict__ bz) {
    __shared__ float lat[LL];
    int b = blockIdx.x;
    for (int k = threadIdx.x; k < LL; k += blockDim.x) lat[k] = latent[b * LL + k];
    __syncthreads();
    for (int j = threadIdx.x; j < HH; j += blockDim.x) {
        const float4* w = (const float4*)(Wz + (size_t)j * LL);
        float s = bz[j];
#pragma unroll 8
        for (int k4 = 0; k4 < LL / 4; ++k4) {
            float4 wv = w[k4];
            s += wv.x * lat[k4 * 4 + 0] + wv.y * lat[k4 * 4 + 1]
               + wv.z * lat[k4 * 4 + 2] + wv.w * lat[k4 * 4 + 3];
        }
        g_h0[b * HH + j] = fmaxf(s, 0.f);
    }
}

// ------------------------------------------------------------------
// Persistent LSTM recurrence. 128 CTAs (1/SM), 512 threads (16 warps).
// CTA m owns units [8m, 8m+8) = 32 gate rows (A slice SMEM-resident all
// 512 steps as k-pair float2). Split-K over 16 warps (64 k each).
// Lane tile: 4 gates of unit (lane&7) x 8 batches (8*(lane>>3)..+8),
// fma.rn.f32x2 inner. h staging coalesced: quarter-warp per batch.
// Grid barrier between steps on g_bar (release/acquire).
// ------------------------------------------------------------------
__global__ void __launch_bounds__(512, 1) k_lstm(
    const float* __restrict__ W_hh,   // [4H, H]
    const float* __restrict__ W_ih,   // [4H, V]
    const float* __restrict__ b_ih,
    const float* __restrict__ b_hh,
    const int*   __restrict__ labels) // [B, T]
{
    extern __shared__ char sm[];
    float* cbias = (float*)(sm + SM_BIAS);

    const int tid  = threadIdx.x;
    const int w    = tid >> 5;
    const int lane = tid & 31;
    const int lr   = lane & 7;    // compute: unit within CTA
    const int lb   = lane >> 3;   // compute: batch group (8 each)
    const int sq   = lane >> 3;   // staging: batch sub (0..3)
    const int sr   = lane & 7;    // staging: k-pair index (0..7)
    const int u0   = blockIdx.x * 8;

    // ---- one-time: W_hh slice -> SMEM as k-pairs (A[kp][u*4+g]) ----
    for (int i = tid; i < 32 * 512; i += 512) {
        int kp = i & 511, row = i >> 9;       // row = u*4+g
        int u = row >> 2, g = row & 3;
        ((float2*)sm)[kp * 32 + u * 4 + g] =
            *(const float2*)(W_hh + (size_t)(g * HH + u0 + u) * HH + 2 * kp);
    }
    if (tid < 32) {
        int u = tid >> 2, g = tid & 3;
        cbias[tid] = b_ih[g * HH + u0 + u] + b_hh[g * HH + u0 + u];
    }

    const int pu = tid & 7;       // pointwise: unit (tid < 256 only)
    const int pb = tid >> 3;      // pointwise: batch 0..31
    float c_loc = 0.f;
    char* buf0 = sm + SM_B + w * SM_BUFW;
    const int k0w = w * 64;       // this warp's k range start
    __syncthreads();

    for (int t = 0; t < TT; ++t) {
        if (t > 0) {
            if (tid == 0) {
                unsigned tgt = 128u * (unsigned)t;
                while (ld_acq(&g_bar) < tgt) {}
            }
            __syncthreads();
        }

        // staging base: batch rows sq, sq+4, ..., sq+28; coalesced float2
        const float* sbase;
        size_t bstride;
        if (t == 0) { sbase = g_h0 + sq * HH;                         bstride = 4 * HH; }
        else        { sbase = g_hs + ((size_t)sq * TT + (t - 1)) * HH; bstride = (size_t)4 * TT * HH; }
        sbase += k0w + 2 * sr;

        float2 pv[8], pvn[8];
#pragma unroll
        for (int i = 0; i < 8; ++i)
            pv[i] = *(const float2*)(sbase + i * bstride);   // sub-chunk 0

        ull acc[4][8];
#pragma unroll
        for (int g = 0; g < 4; ++g)
#pragma unroll
            for (int c = 0; c < 8; ++c) acc[g][c] = 0ull;

#pragma unroll
        for (int sc = 0; sc < 4; ++sc) {
            char* buf = buf0 + (sc & 1) * SM_BUF1;
            // store staged k-pairs: B[kp sr][batch 4i+sq]
#pragma unroll
            for (int i = 0; i < 8; ++i)
                *(float2*)(buf + sr * 272 + (4 * i + sq) * 8) = pv[i];
            __syncwarp();
            if (sc < 3) {
#pragma unroll
                for (int i = 0; i < 8; ++i)
                    pvn[i] = *(const float2*)(sbase + (sc + 1) * 16 + i * bstride);
            }
            const char* Ab = sm + (size_t)(w * 32 + sc * 8) * 256;
#pragma unroll
            for (int kp = 0; kp < 8; ++kp) {
                F4U qa0, qa1;
                qa0.f = *(const float4*)(Ab + kp * 256 + lr * 32);
                qa1.f = *(const float4*)(Ab + kp * 256 + lr * 32 + 16);
                const char* bp = buf + kp * 272 + lb * 64;
                F4U q0, q1, q2, q3;
                q0.f = *(const float4*)(bp);
                q1.f = *(const float4*)(bp + 16);
                q2.f = *(const float4*)(bp + 32);
                q3.f = *(const float4*)(bp + 48);
                ull a0 = qa0.u[0], a1 = qa0.u[1], a2 = qa1.u[0], a3 = qa1.u[1];
                ull b0 = q0.u[0], b1 = q0.u[1], b2 = q1.u[0], b3 = q1.u[1];
                ull b4 = q2.u[0], b5 = q2.u[1], b6 = q3.u[0], b7 = q3.u[1];
                ffma2(acc[0][0], a0, b0); ffma2(acc[0][1], a0, b1);
                ffma2(acc[0][2], a0, b2); ffma2(acc[0][3], a0, b3);
                ffma2(acc[0][4], a0, b4); ffma2(acc[0][5], a0, b5);
                ffma2(acc[0][6], a0, b6); ffma2(acc[0][7], a0, b7);
                ffma2(acc[1][0], a1, b0); ffma2(acc[1][1], a1, b1);
                ffma2(acc[1][2], a1, b2); ffma2(acc[1][3], a1, b3);
                ffma2(acc[1][4], a1, b4); ffma2(acc[1][5], a1, b5);
                ffma2(acc[1][6], a1, b6); ffma2(acc[1][7], a1, b7);
                ffma2(acc[2][0], a2, b0); ffma2(acc[2][1], a2, b1);
                ffma2(acc[2][2], a2, b2); ffma2(acc[2][3], a2, b3);
                ffma2(acc[2][4], a2, b4); ffma2(acc[2][5], a2, b5);
                ffma2(acc[2][6], a2, b6); ffma2(acc[2][7], a2, b7);
                ffma2(acc[3][0], a3, b0); ffma2(acc[3][1], a3, b1);
                ffma2(acc[3][2], a3, b2); ffma2(acc[3][3], a3, b3);
                ffma2(acc[3][4], a3, b4); ffma2(acc[3][5], a3, b5);
                ffma2(acc[3][6], a3, b6); ffma2(acc[3][7], a3, b7);
            }
            __syncwarp();
#pragma unroll
            for (int i = 0; i < 8; ++i) pv[i] = pvn[i];
        }

        // ---- split-K partials into B region (after all buffer reads) ----
        __syncthreads();
        float* P = (float*)(sm + SM_B);   // [w 0..15][b 0..31][u 0..7] float4
#pragma unroll
        for (int c = 0; c < 8; ++c) {
            int b = lb * 8 + c;
            float4 g4 = make_float4(pair_sum(acc[0][c]), pair_sum(acc[1][c]),
                                    pair_sum(acc[2][c]), pair_sum(acc[3][c]));
            *(float4*)(P + ((w * 32 + b) * 8 + lr) * 4) = g4;
        }
        __syncthreads();

        // ---- reduce over 16 warps + pointwise cell (i,f,g,o order) ----
        if (tid < 256) {
            float4 s = make_float4(0.f, 0.f, 0.f, 0.f);
#pragma unroll
            for (int ww = 0; ww < 16; ++ww) {
                float4 pv4 = *(const float4*)(P + ((ww * 32 + pb) * 8 + pu) * 4);
                s.x += pv4.x; s.y += pv4.y; s.z += pv4.z; s.w += pv4.w;
            }
            float gi = s.x + cbias[pu * 4 + 0];
            float gf = s.y + cbias[pu * 4 + 1];
            float gg = s.z + cbias[pu * 4 + 2];
            float go = s.w + cbias[pu * 4 + 3];
            if (t > 0) {   // one-hot input = column gather of W_ih
                int lbl = labels[pb * TT + t - 1];
                int ub  = u0 + pu;
                gi += W_ih[(size_t)(0 * HH + ub) * VV + lbl];
                gf += W_ih[(size_t)(1 * HH + ub) * VV + lbl];
                gg += W_ih[(size_t)(2 * HH + ub) * VV + lbl];
                go += W_ih[(size_t)(3 * HH + ub) * VV + lbl];
            }
            float is = 1.f / (1.f + expf(-gi));
            float fs = 1.f / (1.f + expf(-gf));
            float gt = tanhf(gg);
            float os = 1.f / (1.f + expf(-go));
            c_loc = fs * c_loc + is * gt;
            g_hs[((size_t)pb * TT + t) * HH + u0 + pu] = os * tanhf(c_loc);
        }
        __syncthreads();   // h writes + P reads done before release / reuse
        if (tid == 0) red_rel(&g_bar, 1u);
    }
}

// ------------------------------------------------------------------
// Output head (known-good): fused GEMM->relu->GEMM->log-softmax->
// masked NLL. One CTA = 32 consecutive (b,t) rows.
// ------------------------------------------------------------------
#define OKC 32
#define FP 33
#define WT 68
#define ASP 66
#define WOP 66

__global__ void __launch_bounds__(128) k_out(
    const float* __restrict__ latent,
    const int*   __restrict__ labels,
    const int*   __restrict__ lengths,
    const float* __restrict__ Wnl,   // [H, H+L]
    const float* __restrict__ bnl,
    const float* __restrict__ Wout,  // [V, H]
    const float* __restrict__ bout)
{
    __shared__ float Fs[32 * FP];
    __shared__ float Wst[OKC * WT];
    __shared__ float aS[32 * ASP];
    __shared__ float Wos[VV * WOP];
    __shared__ float Ls[32 * 16];
    __shared__ float lat_s[LL];

    const int tid = threadIdx.x;
    const int r0 = blockIdx.x * 32;
    const int b = r0 / TT;
    const int txj = tid & 15;
    const int tyr = tid >> 4;

    for (int idx = tid; idx < 32 * 16; idx += 128) Ls[idx] = 0.f;
    for (int k = tid; k < LL; k += 128) lat_s[k] = latent[b * LL + k];

    for (int jc = 0; jc < HH; jc += 64) {
        float acc[4][4] = {};
        for (int kc = 0; kc < HH + LL; kc += OKC) {
            __syncthreads();
#pragma unroll
            for (int q = 0; q < 8; ++q) {
                int i = q * 128 + tid;
                int k = i & 31;
                int row = i >> 5;
                int kk = kc + k;
                float v = (kk < HH) ? g_hs[(size_t)(r0 + row) * HH + kk]
                                    : lat_s[kk - HH];
                Fs[row * FP + k] = v;
            }
#pragma unroll
            for (int q = 0; q < 4; ++q) {
                int i = q * 128 + tid;
                int jl = i >> 3;
                int kq = (i & 7) << 2;
                float4 v = *(const float4*)(Wnl + (size_t)(jc + jl) * (HH + LL) + kc + kq);
                Wst[(kq + 0) * WT + jl] = v.x;
                Wst[(kq + 1) * WT + jl] = v.y;
                Wst[(kq + 2) * WT + jl] = v.z;
                Wst[(kq + 3) * WT + jl] = v.w;
            }
            __syncthreads();
#pragma unroll 4
            for (int k = 0; k < OKC; ++k) {
                float4 wv = *(const float4*)(Wst + k * WT + (txj << 2));
                float f0 = Fs[(tyr * 4 + 0) * FP + k];
                float f1 = Fs[(tyr * 4 + 1) * FP + k];
                float f2 = Fs[(tyr * 4 + 2) * FP + k];
                float f3 = Fs[(tyr * 4 + 3) * FP + k];
                acc[0][0] += f0 * wv.x; acc[0][1] += f0 * wv.y; acc[0][2] += f0 * wv.z; acc[0][3] += f0 * wv.w;
                acc[1][0] += f1 * wv.x; acc[1][1] += f1 * wv.y; acc[1][2] += f1 * wv.z; acc[1][3] += f1 * wv.w;
                acc[2][0] += f2 * wv.x; acc[2][1] += f2 * wv.y; acc[2][2] += f2 * wv.z; acc[2][3] += f2 * wv.w;
                acc[3][0] += f3 * wv.x; acc[3][1] += f3 * wv.y; acc[3][2] += f3 * wv.z; acc[3][3] += f3 * wv.w;
            }
        }
        __syncthreads();
#pragma unroll
        for (int ri = 0; ri < 4; ++ri)
#pragma unroll
            for (int ji = 0; ji < 4; ++ji) {
                int j = (txj << 2) + ji;
                aS[(tyr * 4 + ri) * ASP + j] = fmaxf(acc[ri][ji] + bnl[jc + j], 0.f);
            }
        for (int idx = tid; idx < VV * 64; idx += 128) {
            int v = idx >> 6, jl = idx & 63;
            Wos[v * WOP + jl] = Wout[(size_t)v * HH + jc + jl];
        }
        __syncthreads();
        for (int idx = tid; idx < 32 * VV; idx += 128) {
            int row = idx / VV, v = idx - row * VV;
            float s = 0.f;
#pragma unroll 8
            for (int jl = 0; jl < 64; ++jl)
                s += aS[row * ASP + jl] * Wos[v * WOP + jl];
            Ls[row * 16 + v] += s;
        }
        __syncthreads();
    }

    float val = 0.f;
    if (tid < 32) {
        int row = tid;
        int t = (r0 + row) % TT;
        float m = -1e30f;
#pragma unroll
        for (int v = 0; v < VV; ++v) m = fmaxf(m, Ls[row * 16 + v] + bout[v]);
        float s = 0.f;
#pragma unroll
        for (int v = 0; v < VV; ++v) s += expf(Ls[row * 16 + v] + bout[v] - m);
        float lse = m + logf(s);
        int lbl = labels[b * TT + t];
        float nll = lse - (Ls[row * 16 + lbl] + bout[lbl]);
        if (t < lengths[b]) val = nll;
#pragma unroll
        for (int o = 16; o > 0; o >>= 1) val += __shfl_down_sync(0xffffffffu, val, o);
        if (row == 0) g_part[blockIdx.x] = val;
    }
}

// ------------------------------------------------------------------
__global__ void k_final(float* __restrict__ out, int out_size) {
    int b = threadIdx.x;   // 0..31
    float s = 0.f;
#pragma unroll
    for (int i = 0; i < 16; ++i) s += g_part[b * 16 + i];
    if (1 + b < out_size) out[1 + b] = s;
    float tot = s;
#pragma unroll
    for (int o = 16; o > 0; o >>= 1) tot += __shfl_down_sync(0xffffffffu, tot, o);
    if (b == 0) out[0] = tot;
}

// ------------------------------------------------------------------
extern "C" void kernel_launch(void* const* d_in, const int* in_sizes, int n_in,
                              void* d_out, int out_size) {
    const float* latent  = (const float*)d_in[1];
    const int*   labels  = (const int*)d_in[2];
    const int*   lengths = (const int*)d_in[3];
    const float* W_ih    = (const float*)d_in[4];
    const float* W_hh    = (const float*)d_in[5];
    const float* b_ih    = (const float*)d_in[6];
    const float* b_hh    = (const float*)d_in[7];
    const float* Wz      = (const float*)d_in[8];
    const float* bz      = (const float*)d_in[9];
    const float* Wnl     = (const float*)d_in[10];
    const float* bnl     = (const float*)d_in[11];
    const float* Wout    = (const float*)d_in[12];
    const float* bout    = (const float*)d_in[13];
    float* out = (float*)d_out;

    cudaFuncSetAttribute(k_lstm, cudaFuncAttributeMaxDynamicSharedMemorySize, SM_TOTAL);

    k_zero<<<1, 32>>>();
    k_h0<<<BB, 256>>>(latent, Wz, bz);
    k_lstm<<<128, 512, SM_TOTAL>>>(W_hh, W_ih, b_ih, b_hh, labels);
    k_out<<<(BB * TT) / 32, 128>>>(latent, labels, lengths, Wnl, bnl, Wout, bout);
    k_final<<<1, 32>>>(out, out_size);
}

// round 6
// speedup vs baseline: 2.2930x; 1.1018x over previous
#include <cuda_runtime.h>
#include <math.h>

#define BB 32
#define TT 512
#define HH 1024
#define LL 256
#define VV 13

// ---- scratch (static device globals: no allocation allowed) ----
__device__ float g_h0[BB * HH];                 // 128 KB
__device__ float g_hs[(size_t)BB * TT * HH];    // 64 MB, layout [b][t][h]
__device__ float g_part[512];                   // per-CTA loss partials
__device__ unsigned g_bar;                      // software grid barrier counter

typedef unsigned long long ull;
union F4U { float4 f; ull u[2]; };

__device__ __forceinline__ void ffma2(ull& d, ull a, ull b) {
    asm("fma.rn.f32x2 %0, %1, %2, %0;" : "+l"(d) : "l"(a), "l"(b));
}
__device__ __forceinline__ float pair_sum(ull v) {
    float x, y;
    asm("mov.b64 {%0, %1}, %2;" : "=f"(x), "=f"(y) : "l"(v));
    return x + y;
}
__device__ __forceinline__ void unpack2(float& x, float& y, ull v) {
    asm("mov.b64 {%0, %1}, %2;" : "=f"(x), "=f"(y) : "l"(v));
}
__device__ __forceinline__ unsigned ld_acq(const unsigned* p) {
    unsigned v;
    asm volatile("ld.acquire.gpu.global.u32 %0, [%1];" : "=r"(v) : "l"(p) : "memory");
    return v;
}
__device__ __forceinline__ void red_rel(unsigned* p, unsigned v) {
    asm volatile("red.release.gpu.global.add.u32 [%0], %1;" :: "l"(p), "r"(v) : "memory");
}

// SMEM layout for k_lstm (dynamic)
#define SM_A     0
#define SM_B     131072
#define SM_BUF1  2176          // 8 kp * 272
#define SM_BUFW  (2 * SM_BUF1) // 4352 per warp
#define SM_BIAS  (SM_B + 16 * SM_BUFW)   // 200704
#define SM_TOTAL (SM_BIAS + 128)         // 200832

__global__ void k_zero() {
    if (threadIdx.x == 0 && blockIdx.x == 0) g_bar = 0u;
}

// ------------------------------------------------------------------
// h0 = relu(latent @ Wz^T + bz)
// ------------------------------------------------------------------
__global__ void k_h0(const float* __restrict__ latent,
                     const float* __restrict__ Wz,
                     const float* __restrict__ bz) {
    __shared__ float lat[LL];
    int b = blockIdx.x;
    for (int k = threadIdx.x; k < LL; k += blockDim.x) lat[k] = latent[b * LL + k];
    __syncthreads();
    for (int j = threadIdx.x; j < HH; j += blockDim.x) {
        const float4* w = (const float4*)(Wz + (size_t)j * LL);
        float s = bz[j];
#pragma unroll 8
        for (int k4 = 0; k4 < LL / 4; ++k4) {
            float4 wv = w[k4];
            s += wv.x * lat[k4 * 4 + 0] + wv.y * lat[k4 * 4 + 1]
               + wv.z * lat[k4 * 4 + 2] + wv.w * lat[k4 * 4 + 3];
        }
        g_h0[b * HH + j] = fmaxf(s, 0.f);
    }
}

// ------------------------------------------------------------------
// Persistent LSTM recurrence. 128 CTAs (1/SM), 512 threads (16 warps).
// A-tile layout (per kp, 256B): [0..128) = 8 units x gates{0,1} (16B each),
// [128..256) = 8 units x gates{2,3}. Both LDS.128 A loads are contiguous
// 128B per 8-lane phase -> bank-conflict-free (was 2-way on old layout).
// ------------------------------------------------------------------
__global__ void __launch_bounds__(512, 1) k_lstm(
    const float* __restrict__ W_hh,   // [4H, H]
    const float* __restrict__ W_ih,   // [4H, V]
    const float* __restrict__ b_ih,
    const float* __restrict__ b_hh,
    const int*   __restrict__ labels) // [B, T]
{
    extern __shared__ char sm[];
    float* cbias = (float*)(sm + SM_BIAS);

    const int tid  = threadIdx.x;
    const int w    = tid >> 5;
    const int lane = tid & 31;
    const int lr   = lane & 7;    // compute: unit within CTA
    const int lb   = lane >> 3;   // compute: batch group (8 each)
    const int sq   = lane >> 3;   // staging: batch sub (0..3)
    const int sr   = lane & 7;    // staging: k-pair index (0..7)
    const int u0   = blockIdx.x * 8;

    // ---- one-time: W_hh slice -> SMEM, gate-pair-split layout ----
    for (int i = tid; i < 32 * 512; i += 512) {
        int kp = i & 511, row = i >> 9;       // row = u*4+g
        int u = row >> 2, g = row & 3;
        char* dst = sm + kp * 256 + ((g >> 1) << 7) + u * 16 + ((g & 1) << 3);
        *(float2*)dst = *(const float2*)(W_hh + (size_t)(g * HH + u0 + u) * HH + 2 * kp);
    }
    if (tid < 32) {
        int u = tid >> 2, g = tid & 3;
        cbias[tid] = b_ih[g * HH + u0 + u] + b_hh[g * HH + u0 + u];
    }

    const int pu = tid & 7;       // pointwise: unit (tid < 256 only)
    const int pb = tid >> 3;      // pointwise: batch 0..31
    float c_loc = 0.f;
    char* buf0 = sm + SM_B + w * SM_BUFW;
    const int k0w = w * 64;       // this warp's k range start
    __syncthreads();

    for (int t = 0; t < TT; ++t) {
        if (t > 0) {
            if (tid == 0) {
                unsigned tgt = 128u * (unsigned)t;
                while (ld_acq(&g_bar) < tgt) {}
            }
            __syncthreads();
        }

        // staging: quarter-warp per batch row, coalesced float2
        const float* sbase;
        size_t bstride;
        if (t == 0) { sbase = g_h0 + sq * HH;                          bstride = 4 * HH; }
        else        { sbase = g_hs + ((size_t)sq * TT + (t - 1)) * HH; bstride = (size_t)4 * TT * HH; }
        sbase += k0w + 2 * sr;

        float2 pv[8], pvn[8];
#pragma unroll
        for (int i = 0; i < 8; ++i)
            pv[i] = *(const float2*)(sbase + i * bstride);   // sub-chunk 0

        ull acc[4][8];
#pragma unroll
        for (int g = 0; g < 4; ++g)
#pragma unroll
            for (int c = 0; c < 8; ++c) acc[g][c] = 0ull;

#pragma unroll
        for (int sc = 0; sc < 4; ++sc) {
            char* buf = buf0 + (sc & 1) * SM_BUF1;
#pragma unroll
            for (int i = 0; i < 8; ++i)
                *(float2*)(buf + sr * 272 + (4 * i + sq) * 8) = pv[i];
            __syncwarp();
            if (sc < 3) {
#pragma unroll
                for (int i = 0; i < 8; ++i)
                    pvn[i] = *(const float2*)(sbase + (sc + 1) * 16 + i * bstride);
            }
            const char* Ab = sm + (size_t)(w * 32 + sc * 8) * 256;
#pragma unroll
            for (int kp = 0; kp < 8; ++kp) {
                F4U qa0, qa1;
                qa0.f = *(const float4*)(Ab + kp * 256 + lr * 16);        // gates 0,1
                qa1.f = *(const float4*)(Ab + kp * 256 + 128 + lr * 16);  // gates 2,3
                const char* bp = buf + kp * 272 + lb * 64;
                F4U q0, q1, q2, q3;
                q0.f = *(const float4*)(bp);
                q1.f = *(const float4*)(bp + 16);
                q2.f = *(const float4*)(bp + 32);
                q3.f = *(const float4*)(bp + 48);
                ull a0 = qa0.u[0], a1 = qa0.u[1], a2 = qa1.u[0], a3 = qa1.u[1];
                ull b0 = q0.u[0], b1 = q0.u[1], b2 = q1.u[0], b3 = q1.u[1];
                ull b4 = q2.u[0], b5 = q2.u[1], b6 = q3.u[0], b7 = q3.u[1];
                ffma2(acc[0][0], a0, b0); ffma2(acc[0][1], a0, b1);
                ffma2(acc[0][2], a0, b2); ffma2(acc[0][3], a0, b3);
                ffma2(acc[0][4], a0, b4); ffma2(acc[0][5], a0, b5);
                ffma2(acc[0][6], a0, b6); ffma2(acc[0][7], a0, b7);
                ffma2(acc[1][0], a1, b0); ffma2(acc[1][1], a1, b1);
                ffma2(acc[1][2], a1, b2); ffma2(acc[1][3], a1, b3);
                ffma2(acc[1][4], a1, b4); ffma2(acc[1][5], a1, b5);
                ffma2(acc[1][6], a1, b6); ffma2(acc[1][7], a1, b7);
                ffma2(acc[2][0], a2, b0); ffma2(acc[2][1], a2, b1);
                ffma2(acc[2][2], a2, b2); ffma2(acc[2][3], a2, b3);
                ffma2(acc[2][4], a2, b4); ffma2(acc[2][5], a2, b5);
                ffma2(acc[2][6], a2, b6); ffma2(acc[2][7], a2, b7);
                ffma2(acc[3][0], a3, b0); ffma2(acc[3][1], a3, b1);
                ffma2(acc[3][2], a3, b2); ffma2(acc[3][3], a3, b3);
                ffma2(acc[3][4], a3, b4); ffma2(acc[3][5], a3, b5);
                ffma2(acc[3][6], a3, b6); ffma2(acc[3][7], a3, b7);
            }
            __syncwarp();
#pragma unroll
            for (int i = 0; i < 8; ++i) pv[i] = pvn[i];
        }

        // ---- split-K partials into B region (after all buffer reads) ----
        __syncthreads();
        float* P = (float*)(sm + SM_B);   // [w][b][u] float4
#pragma unroll
        for (int c = 0; c < 8; ++c) {
            int b = lb * 8 + c;
            float4 g4 = make_float4(pair_sum(acc[0][c]), pair_sum(acc[1][c]),
                                    pair_sum(acc[2][c]), pair_sum(acc[3][c]));
            *(float4*)(P + ((w * 32 + b) * 8 + lr) * 4) = g4;
        }
        __syncthreads();

        // ---- reduce over 16 warps + pointwise cell (i,f,g,o order) ----
        if (tid < 256) {
            float4 s = make_float4(0.f, 0.f, 0.f, 0.f);
#pragma unroll
            for (int ww = 0; ww < 16; ++ww) {
                float4 pv4 = *(const float4*)(P + ((ww * 32 + pb) * 8 + pu) * 4);
                s.x += pv4.x; s.y += pv4.y; s.z += pv4.z; s.w += pv4.w;
            }
            float gi = s.x + cbias[pu * 4 + 0];
            float gf = s.y + cbias[pu * 4 + 1];
            float gg = s.z + cbias[pu * 4 + 2];
            float go = s.w + cbias[pu * 4 + 3];
            if (t > 0) {
                int lbl = labels[pb * TT + t - 1];
                int ub  = u0 + pu;
                gi += W_ih[(size_t)(0 * HH + ub) * VV + lbl];
                gf += W_ih[(size_t)(1 * HH + ub) * VV + lbl];
                gg += W_ih[(size_t)(2 * HH + ub) * VV + lbl];
                go += W_ih[(size_t)(3 * HH + ub) * VV + lbl];
            }
            float is = 1.f / (1.f + expf(-gi));
            float fs = 1.f / (1.f + expf(-gf));
            float gt = tanhf(gg);
            float os = 1.f / (1.f + expf(-go));
            c_loc = fs * c_loc + is * gt;
            g_hs[((size_t)pb * TT + t) * HH + u0 + pu] = os * tanhf(c_loc);
        }
        __syncthreads();
        if (tid == 0) red_rel(&g_bar, 1u);
    }
}

// ------------------------------------------------------------------
// Output head v2: 256 threads, 64 rows/CTA (grid 256), f32x2 inner.
// Features stored duplicated (float2(v,v)) so the a-operand of each
// ffma2 is one LDS.64 (broadcast). aS aliases the Fs buffer (disjoint
// lifetime within a jc iteration) to stay under the static smem cap.
// ------------------------------------------------------------------
#define OKC 32
#define FP2 33   // Fs2 pitch in float2
#define WT 68
#define ASP 66
#define WOP 66

__global__ void __launch_bounds__(256) k_out(
    const float* __restrict__ latent,
    const int*   __restrict__ labels,
    const int*   __restrict__ lengths,
    const float* __restrict__ Wnl,   // [H, H+L]
    const float* __restrict__ bnl,
    const float* __restrict__ Wout,  // [V, H]
    const float* __restrict__ bout)
{
    __shared__ char FsA[64 * FP2 * 8];   // 16896B: Fs2 during GEMM, aS in epilogue
    __shared__ float Wst[OKC * WT];
    __shared__ float Wos[VV * WOP];
    __shared__ float Ls[64 * 16];
    __shared__ float lat_s[LL];
    __shared__ float red2[2];

    float2* Fs2 = (float2*)FsA;
    float*  aS  = (float*)FsA;

    const int tid = threadIdx.x;
    const int r0 = blockIdx.x * 64;      // 64 rows, all same b (512/64=8)
    const int b = r0 / TT;
    const int txj = tid & 15;            // 4 j each -> 64 j
    const int tyr = tid >> 4;            // 4 rows each -> 64 rows

    for (int idx = tid; idx < 64 * 16; idx += 256) Ls[idx] = 0.f;
    for (int k = tid; k < LL; k += 256) lat_s[k] = latent[b * LL + k];

    for (int jc = 0; jc < HH; jc += 64) {
        ull accp[4][2] = {};
        for (int kc = 0; kc < HH + LL; kc += OKC) {
            __syncthreads();
            // stage features duplicated: 64 rows x 32 k
#pragma unroll
            for (int q = 0; q < 8; ++q) {
                int i = q * 256 + tid;
                int k = i & 31;
                int row = i >> 5;
                int kk = kc + k;
                float v = (kk < HH) ? g_hs[(size_t)(r0 + row) * HH + kk]
                                    : lat_s[kk - HH];
                Fs2[row * FP2 + k] = make_float2(v, v);
            }
            // stage Wnl transposed: 64 j x 32 k
#pragma unroll
            for (int q = 0; q < 2; ++q) {
                int i = q * 256 + tid;           // 0..511 float4
                int jl = i >> 3;
                int kq = (i & 7) << 2;
                float4 v = *(const float4*)(Wnl + (size_t)(jc + jl) * (HH + LL) + kc + kq);
                Wst[(kq + 0) * WT + jl] = v.x;
                Wst[(kq + 1) * WT + jl] = v.y;
                Wst[(kq + 2) * WT + jl] = v.z;
                Wst[(kq + 3) * WT + jl] = v.w;
            }
            __syncthreads();
#pragma unroll 4
            for (int k = 0; k < OKC; ++k) {
                F4U qw;
                qw.f = *(const float4*)(Wst + k * WT + (txj << 2));
                ull b0 = qw.u[0], b1 = qw.u[1];
#pragma unroll
                for (int r = 0; r < 4; ++r) {
                    ull fd = *(const ull*)(Fs2 + (tyr * 4 + r) * FP2 + k);
                    ffma2(accp[r][0], fd, b0);
                    ffma2(accp[r][1], fd, b1);
                }
            }
        }
        __syncthreads();   // all reads of Fs2 done before aS overwrites it
        // relu + bias -> aS
#pragma unroll
        for (int r = 0; r < 4; ++r) {
            float a0, a1, a2, a3;
            unpack2(a0, a1, accp[r][0]);
            unpack2(a2, a3, accp[r][1]);
            int j = txj << 2;
            int row = tyr * 4 + r;
            aS[row * ASP + j + 0] = fmaxf(a0 + bnl[jc + j + 0], 0.f);
            aS[row * ASP + j + 1] = fmaxf(a1 + bnl[jc + j + 1], 0.f);
            aS[row * ASP + j + 2] = fmaxf(a2 + bnl[jc + j + 2], 0.f);
            aS[row * ASP + j + 3] = fmaxf(a3 + bnl[jc + j + 3], 0.f);
        }
        for (int idx = tid; idx < VV * 64; idx += 256) {
            int v = idx >> 6, jl = idx & 63;
            Wos[v * WOP + jl] = Wout[(size_t)v * HH + jc + jl];
        }
        __syncthreads();
        // logits accumulation (tiny GEMM to V=13)
        for (int idx = tid; idx < 64 * VV; idx += 256) {
            int row = idx / VV, v = idx - row * VV;
            float s = 0.f;
#pragma unroll 8
            for (int jl = 0; jl < 64; ++jl)
                s += aS[row * ASP + jl] * Wos[v * WOP + jl];
            Ls[row * 16 + v] += s;
        }
        __syncthreads();
    }

    // log-softmax + masked NLL; deterministic per-CTA partial
    float val = 0.f;
    if (tid < 64) {
        int row = tid;
        int t = (r0 + row) % TT;
        float m = -1e30f;
#pragma unroll
        for (int v = 0; v < VV; ++v) m = fmaxf(m, Ls[row * 16 + v] + bout[v]);
        float s = 0.f;
#pragma unroll
        for (int v = 0; v < VV; ++v) s += expf(Ls[row * 16 + v] + bout[v] - m);
        float lse = m + logf(s);
        int lbl = labels[b * TT + t];
        float nll = lse - (Ls[row * 16 + lbl] + bout[lbl]);
        if (t < lengths[b]) val = nll;
#pragma unroll
        for (int o = 16; o > 0; o >>= 1) val += __shfl_down_sync(0xffffffffu, val, o);
        if ((tid & 31) == 0) red2[tid >> 5] = val;
    }
    __syncthreads();
    if (tid == 0) g_part[blockIdx.x] = red2[0] + red2[1];
}

// ------------------------------------------------------------------
// finalize: 8 partials per batch now (256 CTAs)
// ------------------------------------------------------------------
__global__ void k_final(float* __restrict__ out, int out_size) {
    int b = threadIdx.x;   // 0..31
    float s = 0.f;
#pragma unroll
    for (int i = 0; i < 8; ++i) s += g_part[b * 8 + i];
    if (1 + b < out_size) out[1 + b] = s;
    float tot = s;
#pragma unroll
    for (int o = 16; o > 0; o >>= 1) tot += __shfl_down_sync(0xffffffffu, tot, o);
    if (b == 0) out[0] = tot;
}

// ------------------------------------------------------------------
extern "C" void kernel_launch(void* const* d_in, const int* in_sizes, int n_in,
                              void* d_out, int out_size) {
    const float* latent  = (const float*)d_in[1];
    const int*   labels  = (const int*)d_in[2];
    const int*   lengths = (const int*)d_in[3];
    const float* W_ih    = (const float*)d_in[4];
    const float* W_hh    = (const float*)d_in[5];
    const float* b_ih    = (const float*)d_in[6];
    const float* b_hh    = (const float*)d_in[7];
    const float* Wz      = (const float*)d_in[8];
    const float* bz      = (const float*)d_in[9];
    const float* Wnl     = (const float*)d_in[10];
    const float* bnl     = (const float*)d_in[11];
    const float* Wout    = (const float*)d_in[12];
    const float* bout    = (const float*)d_in[13];
    float* out = (float*)d_out;

    cudaFuncSetAttribute(k_lstm, cudaFuncAttributeMaxDynamicSharedMemorySize, SM_TOTAL);

    k_zero<<<1, 32>>>();
    k_h0<<<BB, 256>>>(latent, Wz, bz);
    k_lstm<<<128, 512, SM_TOTAL>>>(W_hh, W_ih, b_ih, b_hh, labels);
    k_out<<<(BB * TT) / 64, 256>>>(latent, labels, lengths, Wnl, bnl, Wout, bout);
    k_final<<<1, 32>>>(out, out_size);
}